// round 4
// baseline (speedup 1.0000x reference)
#include <cuda_runtime.h>

// Problem constants
#define C_   256
#define N_   12
#define B_   1024
#define NN_  144            // N*N edge features
#define MX_  (B_*N_)        // 12288 node rows
#define ME_  (B_*NN_)       // 147456 edge rows

typedef unsigned long long ull;

// ---------------- scratch (device globals; allocation-free) ----------------
__device__ float  g_Vi[MX_*C_];          // x @ WA^T
__device__ float  g_Vj[MX_*C_];          // x @ WB^T
__device__ float  g_Uj[MX_*C_];          // x @ WV^T (agg values)
__device__ float  g_Ux[MX_*C_];          // x @ WU^T
__device__ float  g_m [(size_t)ME_*C_];  // pre-BN edge message
__device__ float  g_t [MX_*C_];          // pre-BN node update
__device__ double g_sE[NN_],  g_s2E[NN_];
__device__ double g_sV[N_],   g_s2V[N_];
__device__ float  g_aE[NN_],  g_bE[NN_];
__device__ float  g_aV[N_],   g_bV[N_];

// ---------------- f32x2 packed-FMA helpers ----------------
__device__ __forceinline__ ull pack2(float x, float y) {
    ull r; asm("mov.b64 %0, {%1,%2};" : "=l"(r) : "f"(x), "f"(y)); return r;
}
__device__ __forceinline__ ull fma2(ull a, ull b, ull c) {
    ull d; asm("fma.rn.f32x2 %0, %1, %2, %3;" : "=l"(d) : "l"(a), "l"(b), "l"(c)); return d;
}
__device__ __forceinline__ float2 unpack2(ull v) {
    float2 f; asm("mov.b64 {%0,%1}, %2;" : "=f"(f.x), "=f"(f.y) : "l"(v)); return f;
}

// ---------------- 128x128x16 register-blocked GEMM core ----------------
// C[m,n] = sum_k A[m,k] * W[n,k]   (A: [M,256] row-major, W: [256,256] row-major)
// 256 threads, per-thread 8x8 output via f32x2 accumulators.
__device__ __forceinline__ void gemm_core(const float* __restrict__ A,
                                          const float* __restrict__ W,
                                          int rowBase, int colBase,
                                          float As[16][128], float Bs[16][128],
                                          ull acc[8][4])
{
    const int tid  = threadIdx.x;
    const int tx   = tid & 15;
    const int ty   = tid >> 4;
    const int lrow = tid >> 2;          // 0..63
    const int lkq  = (tid & 3) << 2;    // 0,4,8,12

#pragma unroll
    for (int i = 0; i < 8; i++)
#pragma unroll
        for (int p = 0; p < 4; p++) acc[i][p] = 0ULL;

    const float* Ap0 = A + (rowBase + lrow) * 256 + lkq;
    const float* Ap1 = Ap0 + 64 * 256;
    const float* Wp0 = W + (colBase + lrow) * 256 + lkq;
    const float* Wp1 = Wp0 + 64 * 256;

    for (int k0 = 0; k0 < 256; k0 += 16) {
        float4 a0 = *(const float4*)(Ap0 + k0);
        float4 a1 = *(const float4*)(Ap1 + k0);
        float4 w0 = *(const float4*)(Wp0 + k0);
        float4 w1 = *(const float4*)(Wp1 + k0);
        __syncthreads();
        As[lkq + 0][lrow]      = a0.x; As[lkq + 1][lrow]      = a0.y;
        As[lkq + 2][lrow]      = a0.z; As[lkq + 3][lrow]      = a0.w;
        As[lkq + 0][lrow + 64] = a1.x; As[lkq + 1][lrow + 64] = a1.y;
        As[lkq + 2][lrow + 64] = a1.z; As[lkq + 3][lrow + 64] = a1.w;
        Bs[lkq + 0][lrow]      = w0.x; Bs[lkq + 1][lrow]      = w0.y;
        Bs[lkq + 2][lrow]      = w0.z; Bs[lkq + 3][lrow]      = w0.w;
        Bs[lkq + 0][lrow + 64] = w1.x; Bs[lkq + 1][lrow + 64] = w1.y;
        Bs[lkq + 2][lrow + 64] = w1.z; Bs[lkq + 3][lrow + 64] = w1.w;
        __syncthreads();
#pragma unroll
        for (int k = 0; k < 16; k++) {
            float4 av0 = *(const float4*)&As[k][ty * 8];
            float4 av1 = *(const float4*)&As[k][ty * 8 + 4];
            ulonglong2 bq0 = *(const ulonglong2*)&Bs[k][tx * 8];
            ulonglong2 bq1 = *(const ulonglong2*)&Bs[k][tx * 8 + 4];
            ull bp[4] = {bq0.x, bq0.y, bq1.x, bq1.y};
            float av[8] = {av0.x, av0.y, av0.z, av0.w, av1.x, av1.y, av1.z, av1.w};
#pragma unroll
            for (int i = 0; i < 8; i++) {
                ull ai = pack2(av[i], av[i]);
#pragma unroll
                for (int p = 0; p < 4; p++) acc[i][p] = fma2(ai, bp[p], acc[i][p]);
            }
        }
    }
}

// ---------------- K1: the 4 node GEMMs (z selects weight/output) ----------------
__global__ __launch_bounds__(256, 2)
void k_gemm_nodes(const float* __restrict__ x,
                  const float* __restrict__ Wa, const float* __restrict__ Wb,
                  const float* __restrict__ Wv, const float* __restrict__ Wu)
{
    __shared__ __align__(16) float As[16][128];
    __shared__ __align__(16) float Bs[16][128];
    const float* Ws[4] = {Wa, Wb, Wv, Wu};
    float*       Cs[4] = {g_Vi, g_Vj, g_Uj, g_Ux};
    const int z = blockIdx.z;
    const int rowBase = blockIdx.x << 7;
    const int colBase = blockIdx.y << 7;
    ull acc[8][4];
    gemm_core(x, Ws[z], rowBase, colBase, As, Bs, acc);

    const int tx = threadIdx.x & 15, ty = threadIdx.x >> 4;
    float* Cp = Cs[z];
#pragma unroll
    for (int i = 0; i < 8; i++) {
        int r = rowBase + ty * 8 + i;
        float2 v0 = unpack2(acc[i][0]), v1 = unpack2(acc[i][1]);
        float2 v2 = unpack2(acc[i][2]), v3 = unpack2(acc[i][3]);
        float4 o0 = {v0.x, v0.y, v1.x, v1.y};
        float4 o1 = {v2.x, v2.y, v3.x, v3.y};
        *(float4*)&Cp[r * 256 + colBase + tx * 8]     = o0;
        *(float4*)&Cp[r * 256 + colBase + tx * 8 + 4] = o1;
    }
}

// ---------------- K2: edge GEMM + broadcast add + BN stats ----------------
__global__ __launch_bounds__(256, 2)
void k_gemm_edge(const float* __restrict__ edge, const float* __restrict__ We)
{
    __shared__ __align__(16) float As[16][128];
    __shared__ __align__(16) float Bs[16][128];
    __shared__ float rs[128], rs2[128];
    const int rowBase = blockIdx.x << 7;
    const int colBase = blockIdx.y << 7;
    ull acc[8][4];
    gemm_core(edge, We, rowBase, colBase, As, Bs, acc);

    const int tid = threadIdx.x;
    const int tx = tid & 15, ty = tid >> 4;
#pragma unroll
    for (int i = 0; i < 8; i++) {
        int r  = rowBase + ty * 8 + i;
        int b  = r / 144;
        int e  = r - b * 144;
        int ii = e / 12;
        int jj = e - ii * 12;
        const float* vip = &g_Vi[(b * 12 + ii) * 256 + colBase + tx * 8];
        const float* vjp = &g_Vj[(b * 12 + jj) * 256 + colBase + tx * 8];
        float4 vi0 = *(const float4*)vip, vi1 = *(const float4*)(vip + 4);
        float4 vj0 = *(const float4*)vjp, vj1 = *(const float4*)(vjp + 4);
        float2 v0 = unpack2(acc[i][0]), v1 = unpack2(acc[i][1]);
        float2 v2 = unpack2(acc[i][2]), v3 = unpack2(acc[i][3]);
        float m0 = v0.x + vi0.x + vj0.x;
        float m1 = v0.y + vi0.y + vj0.y;
        float m2 = v1.x + vi0.z + vj0.z;
        float m3 = v1.y + vi0.w + vj0.w;
        float m4 = v2.x + vi1.x + vj1.x;
        float m5 = v2.y + vi1.y + vj1.y;
        float m6 = v3.x + vi1.z + vj1.z;
        float m7 = v3.y + vi1.w + vj1.w;
        float4 o0 = {m0, m1, m2, m3}, o1 = {m4, m5, m6, m7};
        *(float4*)&g_m[(size_t)r * 256 + colBase + tx * 8]     = o0;
        *(float4*)&g_m[(size_t)r * 256 + colBase + tx * 8 + 4] = o1;

        float s  = m0 + m1 + m2 + m3 + m4 + m5 + m6 + m7;
        float s2 = m0 * m0 + m1 * m1 + m2 * m2 + m3 * m3 +
                   m4 * m4 + m5 * m5 + m6 * m6 + m7 * m7;
        // reduce over tx (16 lanes of a half-warp share these rows)
#pragma unroll
        for (int o = 1; o < 16; o <<= 1) {
            s  += __shfl_xor_sync(0xffffffffu, s,  o);
            s2 += __shfl_xor_sync(0xffffffffu, s2, o);
        }
        if (tx == 0) { rs[ty * 8 + i] = s; rs2[ty * 8 + i] = s2; }
    }
    __syncthreads();
    if (tid < 128) {
        int r = rowBase + tid;
        int e = r % 144;
        atomicAdd(&g_sE[e],  (double)rs[tid]);
        atomicAdd(&g_s2E[e], (double)rs2[tid]);
    }
}

// ---------------- K3/K5: BN params (then reset accumulators) ----------------
__global__ void k_bn_edge(const float* __restrict__ ge, const float* __restrict__ be)
{
    int i = threadIdx.x;
    if (i < 144) {
        const double inv = 1.0 / (1024.0 * 256.0);
        double mu  = g_sE[i] * inv;
        double var = g_s2E[i] * inv - mu * mu;
        float a = (float)((double)ge[i] * rsqrt(var + 1e-5));
        g_aE[i] = a;
        g_bE[i] = be[i] - a * (float)mu;
        g_sE[i] = 0.0; g_s2E[i] = 0.0;
    }
}
__global__ void k_bn_node(const float* __restrict__ gv, const float* __restrict__ bv)
{
    int i = threadIdx.x;
    if (i < 12) {
        const double inv = 1.0 / (1024.0 * 256.0);
        double mu  = g_sV[i] * inv;
        double var = g_s2V[i] * inv - mu * mu;
        float a = (float)((double)gv[i] * rsqrt(var + 1e-5));
        g_aV[i] = a;
        g_bV[i] = bv[i] - a * (float)mu;
        g_sV[i] = 0.0; g_s2V[i] = 0.0;
    }
}

// ---------------- K4: edge update + sigmoid + softmax_j + aggregation + node stats ----
// One block per (b,i); 256 threads = channels. edge_in/edge_out may alias (in-place safe:
// each element is read then written by the same thread exactly once).
__global__ __launch_bounds__(256)
void k_edge_apply(const float* edge_in, float* edge_out)
{
    const int bi = blockIdx.x;              // b*12 + i
    const int b  = bi / 12;
    const int i  = bi - b * 12;
    const int c  = threadIdx.x;
    const int base = (b * 144 + i * 12) * 256 + c;

    float den = 0.f, ag = 0.f;
#pragma unroll
    for (int j = 0; j < 12; j++) {
        int e = i * 12 + j;
        float mv = g_m[(size_t)base + j * 256];
        float ev = edge_in[base + j * 256];
        float bn = g_aE[e] * mv + g_bE[e];
        float eo = ev + fmaxf(bn, 0.f);
        edge_out[base + j * 256] = eo;
        float sg = 1.f / (1.f + __expf(-eo));
        float ex = __expf(sg);
        den += ex;
        ag  += ex * g_Uj[(b * 12 + j) * 256 + c];
    }
    float tv = g_Ux[bi * 256 + c] + ag / (den * 12.f);
    g_t[bi * 256 + c] = tv;

    // block-reduce node BN stats for feature i
    float s = tv, s2 = tv * tv;
#pragma unroll
    for (int o = 16; o; o >>= 1) {
        s  += __shfl_xor_sync(0xffffffffu, s,  o);
        s2 += __shfl_xor_sync(0xffffffffu, s2, o);
    }
    __shared__ float ws[8], ws2[8];
    int lane = c & 31, w = c >> 5;
    if (lane == 0) { ws[w] = s; ws2[w] = s2; }
    __syncthreads();
    if (c == 0) {
        float ts = 0.f, ts2 = 0.f;
#pragma unroll
        for (int k = 0; k < 8; k++) { ts += ws[k]; ts2 += ws2[k]; }
        atomicAdd(&g_sV[i],  (double)ts);
        atomicAdd(&g_s2V[i], (double)ts2);
    }
}

// ---------------- K6: x = relu(res + bn(t)) (in-place safe) ----------------
__global__ __launch_bounds__(256)
void k_x_apply(const float* x_in, float* x_out)
{
    const int bi = blockIdx.x;      // b*12 + i
    const int i  = bi % 12;
    const int idx = bi * 256 + threadIdx.x;
    float v = x_in[idx] + g_aV[i] * g_t[idx] + g_bV[i];
    x_out[idx] = fmaxf(v, 0.f);
}

// ---------------- driver ----------------
static void run_layer(const float* x, const float* edge_in,
                      const float* WA, const float* WB, const float* WE,
                      const float* WU, const float* WV,
                      const float* gv, const float* bv,
                      const float* ge, const float* be,
                      float* x_out, float* edge_out)
{
    dim3 gn(MX_ / 128, 2, 4);
    k_gemm_nodes<<<gn, 256>>>(x, WA, WB, WV, WU);   // z: 0=Vi(WA) 1=Vj(WB) 2=Uj(WV) 3=Ux(WU)
    dim3 geg(ME_ / 128, 2);
    k_gemm_edge<<<geg, 256>>>(edge_in, WE);
    k_bn_edge<<<1, 160>>>(ge, be);
    k_edge_apply<<<MX_, 256>>>(edge_in, edge_out);
    k_bn_node<<<1, 32>>>(gv, bv);
    k_x_apply<<<MX_, 256>>>(x, x_out);
}

extern "C" void kernel_launch(void* const* d_in, const int* in_sizes, int n_in,
                              void* d_out, int out_size)
{
    (void)in_sizes; (void)n_in; (void)out_size;
    const float* x    = (const float*)d_in[0];
    const float* edge = (const float*)d_in[1];
    const float* WA1 = (const float*)d_in[2],  *WB1 = (const float*)d_in[3];
    const float* WE1 = (const float*)d_in[4],  *WU1 = (const float*)d_in[5];
    const float* WV1 = (const float*)d_in[6];
    const float* WA2 = (const float*)d_in[7],  *WB2 = (const float*)d_in[8];
    const float* WE2 = (const float*)d_in[9],  *WU2 = (const float*)d_in[10];
    const float* WV2 = (const float*)d_in[11];
    const float* gv1 = (const float*)d_in[12], *bv1 = (const float*)d_in[13];
    const float* ge1 = (const float*)d_in[14], *be1 = (const float*)d_in[15];
    const float* gv2 = (const float*)d_in[16], *bv2 = (const float*)d_in[17];
    const float* ge2 = (const float*)d_in[18], *be2 = (const float*)d_in[19];

    float* outX = (float*)d_out;                  // x: [1024,12,256]
    float* outE = outX + MX_ * C_;                // edge: [1024,144,256]

    run_layer(x,    edge, WA1, WB1, WE1, WU1, WV1, gv1, bv1, ge1, be1, outX, outE);
    run_layer(outX, outE, WA2, WB2, WE2, WU2, WV2, gv2, bv2, ge2, be2, outX, outE);
}

// round 5
// speedup vs baseline: 1.0003x; 1.0003x over previous
#include <cuda_runtime.h>

// Problem constants
#define C_   256
#define N_   12
#define B_   1024
#define NN_  144            // N*N edge features
#define MX_  (B_*N_)        // 12288 node rows
#define ME_  (B_*NN_)       // 147456 edge rows

typedef unsigned long long ull;

// ---------------- scratch (device globals; allocation-free) ----------------
__device__ float  g_Vi[MX_*C_];          // x @ WA^T
__device__ float  g_Vj[MX_*C_];          // x @ WB^T
__device__ float  g_Uj[MX_*C_];          // x @ WV^T (agg values)
__device__ float  g_Ux[MX_*C_];          // x @ WU^T
__device__ float  g_m [(size_t)ME_*C_];  // pre-BN edge message
__device__ float  g_t [MX_*C_];          // pre-BN node update
__device__ double g_sE[NN_],  g_s2E[NN_];
__device__ double g_sV[N_],   g_s2V[N_];
__device__ float  g_aE[NN_],  g_bE[NN_];
__device__ float  g_aV[N_],   g_bV[N_];

// ---------------- f32x2 packed-FMA helpers ----------------
__device__ __forceinline__ ull pack2(float x, float y) {
    ull r; asm("mov.b64 %0, {%1,%2};" : "=l"(r) : "f"(x), "f"(y)); return r;
}
__device__ __forceinline__ ull fma2(ull a, ull b, ull c) {
    ull d; asm("fma.rn.f32x2 %0, %1, %2, %3;" : "=l"(d) : "l"(a), "l"(b), "l"(c)); return d;
}
__device__ __forceinline__ float2 unpack2(ull v) {
    float2 f; asm("mov.b64 {%0,%1}, %2;" : "=f"(f.x), "=f"(f.y) : "l"(v)); return f;
}

// ---------------- 128x128x16 register-blocked GEMM core ----------------
// C[m,n] = sum_k A[m,k] * W[n,k]   (A: [M,256] row-major, W: [256,256] row-major)
// 256 threads, per-thread 8x8 output via f32x2 accumulators.
__device__ __forceinline__ void gemm_core(const float* __restrict__ A,
                                          const float* __restrict__ W,
                                          int rowBase, int colBase,
                                          float As[16][128], float Bs[16][128],
                                          ull acc[8][4])
{
    const int tid  = threadIdx.x;
    const int tx   = tid & 15;
    const int ty   = tid >> 4;
    const int lrow = tid >> 2;          // 0..63
    const int lkq  = (tid & 3) << 2;    // 0,4,8,12

#pragma unroll
    for (int i = 0; i < 8; i++)
#pragma unroll
        for (int p = 0; p < 4; p++) acc[i][p] = 0ULL;

    const float* Ap0 = A + (rowBase + lrow) * 256 + lkq;
    const float* Ap1 = Ap0 + 64 * 256;
    const float* Wp0 = W + (colBase + lrow) * 256 + lkq;
    const float* Wp1 = Wp0 + 64 * 256;

    for (int k0 = 0; k0 < 256; k0 += 16) {
        float4 a0 = *(const float4*)(Ap0 + k0);
        float4 a1 = *(const float4*)(Ap1 + k0);
        float4 w0 = *(const float4*)(Wp0 + k0);
        float4 w1 = *(const float4*)(Wp1 + k0);
        __syncthreads();
        As[lkq + 0][lrow]      = a0.x; As[lkq + 1][lrow]      = a0.y;
        As[lkq + 2][lrow]      = a0.z; As[lkq + 3][lrow]      = a0.w;
        As[lkq + 0][lrow + 64] = a1.x; As[lkq + 1][lrow + 64] = a1.y;
        As[lkq + 2][lrow + 64] = a1.z; As[lkq + 3][lrow + 64] = a1.w;
        Bs[lkq + 0][lrow]      = w0.x; Bs[lkq + 1][lrow]      = w0.y;
        Bs[lkq + 2][lrow]      = w0.z; Bs[lkq + 3][lrow]      = w0.w;
        Bs[lkq + 0][lrow + 64] = w1.x; Bs[lkq + 1][lrow + 64] = w1.y;
        Bs[lkq + 2][lrow + 64] = w1.z; Bs[lkq + 3][lrow + 64] = w1.w;
        __syncthreads();
#pragma unroll
        for (int k = 0; k < 16; k++) {
            float4 av0 = *(const float4*)&As[k][ty * 8];
            float4 av1 = *(const float4*)&As[k][ty * 8 + 4];
            ulonglong2 bq0 = *(const ulonglong2*)&Bs[k][tx * 8];
            ulonglong2 bq1 = *(const ulonglong2*)&Bs[k][tx * 8 + 4];
            ull bp[4] = {bq0.x, bq0.y, bq1.x, bq1.y};
            float av[8] = {av0.x, av0.y, av0.z, av0.w, av1.x, av1.y, av1.z, av1.w};
#pragma unroll
            for (int i = 0; i < 8; i++) {
                ull ai = pack2(av[i], av[i]);
#pragma unroll
                for (int p = 0; p < 4; p++) acc[i][p] = fma2(ai, bp[p], acc[i][p]);
            }
        }
    }
}

// ---------------- K1: the 4 node GEMMs (z selects weight/output) ----------------
__global__ __launch_bounds__(256, 2)
void k_gemm_nodes(const float* __restrict__ x,
                  const float* __restrict__ Wa, const float* __restrict__ Wb,
                  const float* __restrict__ Wv, const float* __restrict__ Wu)
{
    __shared__ __align__(16) float As[16][128];
    __shared__ __align__(16) float Bs[16][128];
    const float* Ws[4] = {Wa, Wb, Wv, Wu};
    float*       Cs[4] = {g_Vi, g_Vj, g_Uj, g_Ux};
    const int z = blockIdx.z;
    const int rowBase = blockIdx.x << 7;
    const int colBase = blockIdx.y << 7;
    ull acc[8][4];
    gemm_core(x, Ws[z], rowBase, colBase, As, Bs, acc);

    const int tx = threadIdx.x & 15, ty = threadIdx.x >> 4;
    float* Cp = Cs[z];
#pragma unroll
    for (int i = 0; i < 8; i++) {
        int r = rowBase + ty * 8 + i;
        float2 v0 = unpack2(acc[i][0]), v1 = unpack2(acc[i][1]);
        float2 v2 = unpack2(acc[i][2]), v3 = unpack2(acc[i][3]);
        float4 o0 = {v0.x, v0.y, v1.x, v1.y};
        float4 o1 = {v2.x, v2.y, v3.x, v3.y};
        *(float4*)&Cp[r * 256 + colBase + tx * 8]     = o0;
        *(float4*)&Cp[r * 256 + colBase + tx * 8 + 4] = o1;
    }
}

// ---------------- K2: edge GEMM + broadcast add + BN stats ----------------
__global__ __launch_bounds__(256, 2)
void k_gemm_edge(const float* __restrict__ edge, const float* __restrict__ We)
{
    __shared__ __align__(16) float As[16][128];
    __shared__ __align__(16) float Bs[16][128];
    __shared__ float rs[128], rs2[128];
    const int rowBase = blockIdx.x << 7;
    const int colBase = blockIdx.y << 7;
    ull acc[8][4];
    gemm_core(edge, We, rowBase, colBase, As, Bs, acc);

    const int tid = threadIdx.x;
    const int tx = tid & 15, ty = tid >> 4;
#pragma unroll
    for (int i = 0; i < 8; i++) {
        int r  = rowBase + ty * 8 + i;
        int b  = r / 144;
        int e  = r - b * 144;
        int ii = e / 12;
        int jj = e - ii * 12;
        const float* vip = &g_Vi[(b * 12 + ii) * 256 + colBase + tx * 8];
        const float* vjp = &g_Vj[(b * 12 + jj) * 256 + colBase + tx * 8];
        float4 vi0 = *(const float4*)vip, vi1 = *(const float4*)(vip + 4);
        float4 vj0 = *(const float4*)vjp, vj1 = *(const float4*)(vjp + 4);
        float2 v0 = unpack2(acc[i][0]), v1 = unpack2(acc[i][1]);
        float2 v2 = unpack2(acc[i][2]), v3 = unpack2(acc[i][3]);
        float m0 = v0.x + vi0.x + vj0.x;
        float m1 = v0.y + vi0.y + vj0.y;
        float m2 = v1.x + vi0.z + vj0.z;
        float m3 = v1.y + vi0.w + vj0.w;
        float m4 = v2.x + vi1.x + vj1.x;
        float m5 = v2.y + vi1.y + vj1.y;
        float m6 = v3.x + vi1.z + vj1.z;
        float m7 = v3.y + vi1.w + vj1.w;
        float4 o0 = {m0, m1, m2, m3}, o1 = {m4, m5, m6, m7};
        *(float4*)&g_m[(size_t)r * 256 + colBase + tx * 8]     = o0;
        *(float4*)&g_m[(size_t)r * 256 + colBase + tx * 8 + 4] = o1;

        float s  = m0 + m1 + m2 + m3 + m4 + m5 + m6 + m7;
        float s2 = m0 * m0 + m1 * m1 + m2 * m2 + m3 * m3 +
                   m4 * m4 + m5 * m5 + m6 * m6 + m7 * m7;
        // reduce over tx (16 lanes of a half-warp share these rows)
#pragma unroll
        for (int o = 1; o < 16; o <<= 1) {
            s  += __shfl_xor_sync(0xffffffffu, s,  o);
            s2 += __shfl_xor_sync(0xffffffffu, s2, o);
        }
        if (tx == 0) { rs[ty * 8 + i] = s; rs2[ty * 8 + i] = s2; }
    }
    __syncthreads();
    if (tid < 128) {
        int r = rowBase + tid;
        int e = r % 144;
        atomicAdd(&g_sE[e],  (double)rs[tid]);
        atomicAdd(&g_s2E[e], (double)rs2[tid]);
    }
}

// ---------------- K3/K5: BN params (then reset accumulators) ----------------
__global__ void k_bn_edge(const float* __restrict__ ge, const float* __restrict__ be)
{
    int i = threadIdx.x;
    if (i < 144) {
        const double inv = 1.0 / (1024.0 * 256.0);
        double mu  = g_sE[i] * inv;
        double var = g_s2E[i] * inv - mu * mu;
        float a = (float)((double)ge[i] * rsqrt(var + 1e-5));
        g_aE[i] = a;
        g_bE[i] = be[i] - a * (float)mu;
        g_sE[i] = 0.0; g_s2E[i] = 0.0;
    }
}
__global__ void k_bn_node(const float* __restrict__ gv, const float* __restrict__ bv)
{
    int i = threadIdx.x;
    if (i < 12) {
        const double inv = 1.0 / (1024.0 * 256.0);
        double mu  = g_sV[i] * inv;
        double var = g_s2V[i] * inv - mu * mu;
        float a = (float)((double)gv[i] * rsqrt(var + 1e-5));
        g_aV[i] = a;
        g_bV[i] = bv[i] - a * (float)mu;
        g_sV[i] = 0.0; g_s2V[i] = 0.0;
    }
}

// ---------------- K4: edge update + sigmoid + softmax_j + aggregation + node stats ----
// One block per (b,i); 256 threads = channels. edge_in/edge_out may alias (in-place safe:
// each element is read then written by the same thread exactly once).
__global__ __launch_bounds__(256)
void k_edge_apply(const float* edge_in, float* edge_out)
{
    const int bi = blockIdx.x;              // b*12 + i
    const int b  = bi / 12;
    const int i  = bi - b * 12;
    const int c  = threadIdx.x;
    const int base = (b * 144 + i * 12) * 256 + c;

    float den = 0.f, ag = 0.f;
#pragma unroll
    for (int j = 0; j < 12; j++) {
        int e = i * 12 + j;
        float mv = g_m[(size_t)base + j * 256];
        float ev = edge_in[base + j * 256];
        float bn = g_aE[e] * mv + g_bE[e];
        float eo = ev + fmaxf(bn, 0.f);
        edge_out[base + j * 256] = eo;
        float sg = 1.f / (1.f + __expf(-eo));
        float ex = __expf(sg);
        den += ex;
        ag  += ex * g_Uj[(b * 12 + j) * 256 + c];
    }
    float tv = g_Ux[bi * 256 + c] + ag / (den * 12.f);
    g_t[bi * 256 + c] = tv;

    // block-reduce node BN stats for feature i
    float s = tv, s2 = tv * tv;
#pragma unroll
    for (int o = 16; o; o >>= 1) {
        s  += __shfl_xor_sync(0xffffffffu, s,  o);
        s2 += __shfl_xor_sync(0xffffffffu, s2, o);
    }
    __shared__ float ws[8], ws2[8];
    int lane = c & 31, w = c >> 5;
    if (lane == 0) { ws[w] = s; ws2[w] = s2; }
    __syncthreads();
    if (c == 0) {
        float ts = 0.f, ts2 = 0.f;
#pragma unroll
        for (int k = 0; k < 8; k++) { ts += ws[k]; ts2 += ws2[k]; }
        atomicAdd(&g_sV[i],  (double)ts);
        atomicAdd(&g_s2V[i], (double)ts2);
    }
}

// ---------------- K6: x = relu(res + bn(t)) (in-place safe) ----------------
__global__ __launch_bounds__(256)
void k_x_apply(const float* x_in, float* x_out)
{
    const int bi = blockIdx.x;      // b*12 + i
    const int i  = bi % 12;
    const int idx = bi * 256 + threadIdx.x;
    float v = x_in[idx] + g_aV[i] * g_t[idx] + g_bV[i];
    x_out[idx] = fmaxf(v, 0.f);
}

// ---------------- driver ----------------
static void run_layer(const float* x, const float* edge_in,
                      const float* WA, const float* WB, const float* WE,
                      const float* WU, const float* WV,
                      const float* gv, const float* bv,
                      const float* ge, const float* be,
                      float* x_out, float* edge_out)
{
    dim3 gn(MX_ / 128, 2, 4);
    k_gemm_nodes<<<gn, 256>>>(x, WA, WB, WV, WU);   // z: 0=Vi(WA) 1=Vj(WB) 2=Uj(WV) 3=Ux(WU)
    dim3 geg(ME_ / 128, 2);
    k_gemm_edge<<<geg, 256>>>(edge_in, WE);
    k_bn_edge<<<1, 160>>>(ge, be);
    k_edge_apply<<<MX_, 256>>>(edge_in, edge_out);
    k_bn_node<<<1, 32>>>(gv, bv);
    k_x_apply<<<MX_, 256>>>(x, x_out);
}

extern "C" void kernel_launch(void* const* d_in, const int* in_sizes, int n_in,
                              void* d_out, int out_size)
{
    (void)in_sizes; (void)n_in; (void)out_size;
    const float* x    = (const float*)d_in[0];
    const float* edge = (const float*)d_in[1];
    const float* WA1 = (const float*)d_in[2],  *WB1 = (const float*)d_in[3];
    const float* WE1 = (const float*)d_in[4],  *WU1 = (const float*)d_in[5];
    const float* WV1 = (const float*)d_in[6];
    const float* WA2 = (const float*)d_in[7],  *WB2 = (const float*)d_in[8];
    const float* WE2 = (const float*)d_in[9],  *WU2 = (const float*)d_in[10];
    const float* WV2 = (const float*)d_in[11];
    const float* gv1 = (const float*)d_in[12], *bv1 = (const float*)d_in[13];
    const float* ge1 = (const float*)d_in[14], *be1 = (const float*)d_in[15];
    const float* gv2 = (const float*)d_in[16], *bv2 = (const float*)d_in[17];
    const float* ge2 = (const float*)d_in[18], *be2 = (const float*)d_in[19];

    float* outX = (float*)d_out;                  // x: [1024,12,256]
    float* outE = outX + MX_ * C_;                // edge: [1024,144,256]

    run_layer(x,    edge, WA1, WB1, WE1, WU1, WV1, gv1, bv1, ge1, be1, outX, outE);
    run_layer(outX, outE, WA2, WB2, WE2, WU2, WV2, gv2, bv2, ge2, be2, outX, outE);
}